// round 4
// baseline (speedup 1.0000x reference)
#include <cuda_runtime.h>

// RNNModel: h_t = tanh(x_t @ W_ih^T + b_ih + h_{t-1} @ W_hh^T + b_hh); out = h_T @ fc_W^T + fc_b
// B=4096, T=512, D_IN=8, H=50, D_OUT=1
//
// R4: warp-synchronous design. Warp = one batch. Lane u<25 owns units (2u,2u+1)
// with packed W rows in registers (f32x2 FFMA2). Hidden state augmented with x
// (K=58) lives duplicated (h,h) in a per-warp double-buffered shared array and is
// read via all-lanes-same-address broadcast LDS.128. Lanes 25-28 stage next-step
// x dup-packs. One __syncwarp per step -- no block barriers, no cross-warp coupling.

#define B_SZ   4096
#define T_SZ   512
#define DIN    8
#define H_SZ   50
#define KAUG   58                  // 50 h-units + 8 x-inputs (augmented)
#define WPB    8                   // warps (=batches) per block
#define NTHR   (WPB * 32)

typedef unsigned long long ull;

__device__ __forceinline__ ull pack2(float lo, float hi) {
    ull r; asm("mov.b64 %0, {%1, %2};" : "=l"(r) : "f"(lo), "f"(hi)); return r;
}
__device__ __forceinline__ void unpack2(ull v, float& lo, float& hi) {
    asm("mov.b64 {%0, %1}, %2;" : "=f"(lo), "=f"(hi) : "l"(v));
}
__device__ __forceinline__ ull fma2(ull a, ull b, ull c) {
    ull r; asm("fma.rn.f32x2 %0, %1, %2, %3;" : "=l"(r) : "l"(a), "l"(b), "l"(c)); return r;
}
__device__ __forceinline__ ull add2(ull a, ull b) {
    ull r; asm("add.rn.f32x2 %0, %1, %2;" : "=l"(r) : "l"(a), "l"(b)); return r;
}
__device__ __forceinline__ float tanh_fast(float v) {
    // tanh(v) = 1 - 2/(exp(2v)+1); robust at extremes, ~1e-7 rel err
    float e = __expf(2.0f * v);
    return 1.0f - __fdividef(2.0f, e + 1.0f);
}

__global__ void __launch_bounds__(NTHR, 2)
rnn_kernel(const float* __restrict__ x,
           const float* __restrict__ Wih,
           const float* __restrict__ Whh,
           const float* __restrict__ bih,
           const float* __restrict__ bhh,
           const float* __restrict__ fcW,
           const float* __restrict__ fcb,
           float* __restrict__ out)
{
    // per-warp double-buffered augmented state, duplicated packs (v,v).
    // 8 warps * 2 bufs * 64 ull = 8 KB
    __shared__ ull sh[WPB][2][64];

    const int tid  = threadIdx.x;
    const int wrp  = tid >> 5;
    const int lane = tid & 31;
    const int b    = blockIdx.x * WPB + wrp;     // grid sized so b < B_SZ
    const float* __restrict__ xrow = x + (size_t)b * T_SZ * DIN;

    ull* __restrict__ buf0 = sh[wrp][0];
    ull* __restrict__ buf1 = sh[wrp][1];

    // Augmented weight rows, packed over the lane's two units:
    // Wa[k] = (W[j0][k], W[j1][k]) for k<50 (W_hh), then W_ih for k=50..57.
    ull Wa[KAUG];
    ull bias2 = 0;
    const int j0 = 2 * lane, j1 = 2 * lane + 1;

    if (lane < 25) {
#pragma unroll
        for (int k = 0; k < H_SZ; k++)
            Wa[k] = pack2(Whh[j0 * H_SZ + k], Whh[j1 * H_SZ + k]);
#pragma unroll
        for (int d = 0; d < DIN; d++)
            Wa[H_SZ + d] = pack2(Wih[j0 * DIN + d], Wih[j1 * DIN + d]);
        bias2 = pack2(bih[j0] + bhh[j0], bih[j1] + bhh[j1]);
        buf0[j0] = 0ull;            // h0 = 0 (duplicated zero)
        buf0[j1] = 0ull;
    } else if (lane < 29) {
        const int d = (lane - 25) * 2;           // d in {0,2,4,6}
        float xa = xrow[d];
        float xb = xrow[d + 1];
        buf0[H_SZ + d]     = pack2(xa, xa);      // x_0 dup-packs
        buf0[H_SZ + d + 1] = pack2(xb, xb);
    }
    __syncwarp();

    float v0 = 0.f, v1 = 0.f;

#pragma unroll 1
    for (int t = 0; t < T_SZ; t += 2) {
        // ---------- step t: read buf0 -> write buf1; stage x_{t+1} into buf1
        if (lane < 25) {
            ull a0 = bias2;
            ull a1 = pack2(0.f, 0.f);
            const ulonglong2* __restrict__ hp = (const ulonglong2*)buf0;
#pragma unroll
            for (int k2 = 0; k2 < KAUG / 2; k2++) {      // 29 broadcast LDS.128
                ulonglong2 hh = hp[k2];
                a0 = fma2(hh.x, Wa[2 * k2],     a0);
                a1 = fma2(hh.y, Wa[2 * k2 + 1], a1);
            }
            float p0, p1; unpack2(add2(a0, a1), p0, p1);
            v0 = tanh_fast(p0);
            v1 = tanh_fast(p1);
            ulonglong2 wv; wv.x = pack2(v0, v0); wv.y = pack2(v1, v1);
            ((ulonglong2*)buf1)[lane] = wv;              // STS.128, conflict-free
        } else if (lane < 29) {
            const int tn = t + 1;                         // <= 511, no clamp needed
            const int d  = (lane - 25) * 2;
            float xa = xrow[tn * DIN + d];
            float xb = xrow[tn * DIN + d + 1];
            buf1[H_SZ + d]     = pack2(xa, xa);
            buf1[H_SZ + d + 1] = pack2(xb, xb);
        }
        __syncwarp();

        // ---------- step t+1: read buf1 -> write buf0; stage x_{t+2} into buf0
        if (lane < 25) {
            ull a0 = bias2;
            ull a1 = pack2(0.f, 0.f);
            const ulonglong2* __restrict__ hp = (const ulonglong2*)buf1;
#pragma unroll
            for (int k2 = 0; k2 < KAUG / 2; k2++) {
                ulonglong2 hh = hp[k2];
                a0 = fma2(hh.x, Wa[2 * k2],     a0);
                a1 = fma2(hh.y, Wa[2 * k2 + 1], a1);
            }
            float p0, p1; unpack2(add2(a0, a1), p0, p1);
            v0 = tanh_fast(p0);
            v1 = tanh_fast(p1);
            ulonglong2 wv; wv.x = pack2(v0, v0); wv.y = pack2(v1, v1);
            ((ulonglong2*)buf0)[lane] = wv;
        } else if (lane < 29) {
            const int tn = (t + 2 < T_SZ) ? (t + 2) : (T_SZ - 1);  // clamp last
            const int d  = (lane - 25) * 2;
            float xa = xrow[tn * DIN + d];
            float xb = xrow[tn * DIN + d + 1];
            buf0[H_SZ + d]     = pack2(xa, xa);
            buf0[H_SZ + d + 1] = pack2(xb, xb);
        }
        __syncwarp();
    }

    // fc readout: out[b] = sum_j h_T[j] * fcW[j] + fcb[0]
    float part = 0.f;
    if (lane < 25)
        part = v0 * fcW[j0] + v1 * fcW[j1];
#pragma unroll
    for (int off = 16; off; off >>= 1)
        part += __shfl_down_sync(0xffffffffu, part, off);
    if (lane == 0)
        out[b] = part + fcb[0];
}

extern "C" void kernel_launch(void* const* d_in, const int* in_sizes, int n_in,
                              void* d_out, int out_size)
{
    const float* x   = (const float*)d_in[0];
    const float* Wih = (const float*)d_in[1];
    const float* Whh = (const float*)d_in[2];
    const float* bih = (const float*)d_in[3];
    const float* bhh = (const float*)d_in[4];
    const float* fcW = (const float*)d_in[5];
    const float* fcb = (const float*)d_in[6];
    float* out = (float*)d_out;

    rnn_kernel<<<B_SZ / WPB, NTHR>>>(x, Wih, Whh, bih, bhh, fcW, fcb, out);
}

// round 5
// speedup vs baseline: 1.9070x; 1.9070x over previous
#include <cuda_runtime.h>

// RNNModel: h_t = tanh(x_t @ W_ih^T + b_ih + h_{t-1} @ W_hh^T + b_hh); out = h_T @ fc_W^T + fc_b
// B=4096, T=512, D_IN=8, H=50, D_OUT=1
//
// R5: warp-per-batch, k-pair-packed FFMA2.
//   acc2_j = (sum over even k, sum over odd k); each FFMA2 multiplies a natural
//   consecutive h-pair (h_k,h_{k+1}) (straight from a plain-layout LDS.128, NO
//   duplication) by a register-resident W-pair (W_jk,W_jk+1). 13 LDS.128 per
//   step instead of 29 dup-loads -> L1tex wavefront pressure halved.
//   x_t is warp-uniform: 2 broadcast LDG.128 feed 4 FFMA2 directly (no smem
//   staging, no divergent branches in the loop). Lanes 25..31 run clamped
//   weight rows and write to pad slots -> branch-free loop body.

#define B_SZ 4096
#define T_SZ 512
#define DIN  8
#define H_SZ 50
#define WPB  8                   // warps (=batches) per block
#define NTHR (WPB * 32)

typedef unsigned long long ull;

__device__ __forceinline__ ull pack2(float lo, float hi) {
    ull r; asm("mov.b64 %0, {%1, %2};" : "=l"(r) : "f"(lo), "f"(hi)); return r;
}
__device__ __forceinline__ void unpack2(ull v, float& lo, float& hi) {
    asm("mov.b64 {%0, %1}, %2;" : "=f"(lo), "=f"(hi) : "l"(v));
}
__device__ __forceinline__ ull fma2(ull a, ull b, ull c) {
    ull r; asm("fma.rn.f32x2 %0, %1, %2, %3;" : "=l"(r) : "l"(a), "l"(b), "l"(c)); return r;
}
__device__ __forceinline__ float tanh_fast(float v) {
    // tanh(v) = 1 - 2/(exp(2v)+1); robust at extremes, ~1e-7 rel err
    float e = __expf(2.0f * v);
    return 1.0f - __fdividef(2.0f, e + 1.0f);
}

__global__ void __launch_bounds__(NTHR, 2)
rnn_kernel(const float* __restrict__ x,
           const float* __restrict__ Wih,
           const float* __restrict__ Whh,
           const float* __restrict__ bih,
           const float* __restrict__ bhh,
           const float* __restrict__ fcW,
           const float* __restrict__ fcb,
           float* __restrict__ out)
{
    // plain (non-duplicated) h, double buffered, padded to 64 floats per buf.
    // 8 warps * 2 * 64 * 4B = 4 KB
    __shared__ float hb[WPB][2][64];

    const int tid  = threadIdx.x;
    const int w    = tid >> 5;
    const int lane = tid & 31;
    const int b    = blockIdx.x * WPB + w;

    // lanes 25..31: clamp to valid rows (compute harmless duplicates into pad)
    const int j0 = 2 * lane;
    const int r0 = (j0     < H_SZ) ? j0     : (H_SZ - 1);
    const int r1 = (j0 + 1 < H_SZ) ? j0 + 1 : (H_SZ - 1);

    // W pairs in registers: q<25 from W_hh (cols 2q,2q+1), q=25..28 from W_ih.
    ull W0[29], W1[29];
#pragma unroll
    for (int q = 0; q < 25; q++) {
        W0[q] = pack2(Whh[r0 * H_SZ + 2 * q], Whh[r0 * H_SZ + 2 * q + 1]);
        W1[q] = pack2(Whh[r1 * H_SZ + 2 * q], Whh[r1 * H_SZ + 2 * q + 1]);
    }
#pragma unroll
    for (int d = 0; d < 4; d++) {
        W0[25 + d] = pack2(Wih[r0 * DIN + 2 * d], Wih[r0 * DIN + 2 * d + 1]);
        W1[25 + d] = pack2(Wih[r1 * DIN + 2 * d], Wih[r1 * DIN + 2 * d + 1]);
    }
    const ull b0p = pack2(bih[r0] + bhh[r0], 0.0f);   // bias rides the even half
    const ull b1p = pack2(bih[r1] + bhh[r1], 0.0f);

    // zero both buffers (h0 = 0; pad slots must be finite)
#pragma unroll
    for (int i = tid; i < WPB * 2 * 64; i += NTHR)
        (&hb[0][0][0])[i] = 0.0f;
    __syncthreads();

    // x row for this batch, viewed as packed pairs: xq[2t]=(x0,x1|x2,x3), xq[2t+1]=(x4..x7)
    const ulonglong2* __restrict__ xq =
        (const ulonglong2*)(x + (size_t)b * T_SZ * DIN);

    float v0 = 0.f, v1 = 0.f;

#pragma unroll 1
    for (int t = 0; t < T_SZ; t += 2) {
#pragma unroll
        for (int half = 0; half < 2; half++) {
            const int   tt  = t + half;
            const int   cur = half;          // read buf `half`, write buf `half^1`
            const ulonglong2 xA = xq[2 * tt];
            const ulonglong2 xB = xq[2 * tt + 1];

            // input projection (x pairs are already packed; warp-uniform broadcast loads)
            ull a0 = fma2(xA.x, W0[25], b0p);
            ull a1 = fma2(xA.x, W1[25], b1p);
            a0 = fma2(xA.y, W0[26], a0);  a1 = fma2(xA.y, W1[26], a1);
            a0 = fma2(xB.x, W0[27], a0);  a1 = fma2(xB.x, W1[27], a1);
            a0 = fma2(xB.y, W0[28], a0);  a1 = fma2(xB.y, W1[28], a1);

            // recurrence: 12 x LDS.128 (4 h each) + 1 x LDS.64 (h48,h49)
            const ulonglong2* __restrict__ hp = (const ulonglong2*)hb[w][cur];
#pragma unroll
            for (int p = 0; p < 12; p++) {
                ulonglong2 hh = hp[p];                    // (h4p,h4p+1),(h4p+2,h4p+3)
                a0 = fma2(hh.x, W0[2 * p],     a0);
                a1 = fma2(hh.x, W1[2 * p],     a1);
                a0 = fma2(hh.y, W0[2 * p + 1], a0);
                a1 = fma2(hh.y, W1[2 * p + 1], a1);
            }
            {
                ull h24 = ((const ull*)hb[w][cur])[24];   // (h48,h49)
                a0 = fma2(h24, W0[24], a0);
                a1 = fma2(h24, W1[24], a1);
            }

            float e0, o0; unpack2(a0, e0, o0);
            float e1, o1; unpack2(a1, e1, o1);
            v0 = tanh_fast(e0 + o0);
            v1 = tanh_fast(e1 + o1);

            // plain store of the lane's two units (pad writes for lanes>=25)
            *(float2*)&hb[w][cur ^ 1][j0] = make_float2(v0, v1);
            __syncwarp();
        }
    }

    // fc readout: out[b] = sum_j h_T[j]*fcW[j] + fcb[0]
    float part = 0.f;
    if (lane < 25)
        part = v0 * fcW[j0] + v1 * fcW[j0 + 1];
#pragma unroll
    for (int off = 16; off; off >>= 1)
        part += __shfl_down_sync(0xffffffffu, part, off);
    if (lane == 0)
        out[b] = part + fcb[0];
}

extern "C" void kernel_launch(void* const* d_in, const int* in_sizes, int n_in,
                              void* d_out, int out_size)
{
    const float* x   = (const float*)d_in[0];
    const float* Wih = (const float*)d_in[1];
    const float* Whh = (const float*)d_in[2];
    const float* bih = (const float*)d_in[3];
    const float* bhh = (const float*)d_in[4];
    const float* fcW = (const float*)d_in[5];
    const float* fcb = (const float*)d_in[6];
    float* out = (float*)d_out;

    rnn_kernel<<<B_SZ / WPB, NTHR>>>(x, Wih, Whh, bih, bhh, fcW, fcb, out);
}

// round 10
// speedup vs baseline: 2.5746x; 1.3501x over previous
#include <cuda_runtime.h>

// RNNModel: h_t = tanh(x_t @ W_ih^T + b_ih + h_{t-1} @ W_hh^T + b_hh); out = h_T @ fc_W^T + fc_b
// B=4096, T=512, D_IN=8, H=50, D_OUT=1
//
// R6: R5 k-pair-packed FFMA2 design, with the register cap removed.
//   R5 had __launch_bounds__(256,2) -> 128-reg cap, but W0+W1 = 116 regs -> ptxas
//   spilled ~20 regs; the spilled W pairs were reloaded via LDL inside the inner
//   loop every step (L1=60%, issue=33%). Fix: 128-thread blocks with
//   __launch_bounds__(128,3) -> 166 regs available, W fully register-resident.
//   Also split each 29-deep accumulator chain into even/odd halves -> 4 chains
//   ~15 deep, cutting per-step dependency latency ~2x for 3-warp/SMSP hiding.

#define B_SZ 4096
#define T_SZ 512
#define DIN  8
#define H_SZ 50
#define WPB  4                   // warps (=batches) per block
#define NTHR (WPB * 32)          // 128

typedef unsigned long long ull;

__device__ __forceinline__ ull pack2(float lo, float hi) {
    ull r; asm("mov.b64 %0, {%1, %2};" : "=l"(r) : "f"(lo), "f"(hi)); return r;
}
__device__ __forceinline__ void unpack2(ull v, float& lo, float& hi) {
    asm("mov.b64 {%0, %1}, %2;" : "=f"(lo), "=f"(hi) : "l"(v));
}
__device__ __forceinline__ ull fma2(ull a, ull b, ull c) {
    ull r; asm("fma.rn.f32x2 %0, %1, %2, %3;" : "=l"(r) : "l"(a), "l"(b), "l"(c)); return r;
}
__device__ __forceinline__ ull add2(ull a, ull b) {
    ull r; asm("add.rn.f32x2 %0, %1, %2;" : "=l"(r) : "l"(a), "l"(b)); return r;
}
__device__ __forceinline__ float tanh_fast(float v) {
    // tanh(v) = 1 - 2/(exp(2v)+1); robust at extremes, ~1e-7 rel err
    float e = __expf(2.0f * v);
    return 1.0f - __fdividef(2.0f, e + 1.0f);
}

__global__ void __launch_bounds__(NTHR, 3)
rnn_kernel(const float* __restrict__ x,
           const float* __restrict__ Wih,
           const float* __restrict__ Whh,
           const float* __restrict__ bih,
           const float* __restrict__ bhh,
           const float* __restrict__ fcW,
           const float* __restrict__ fcb,
           float* __restrict__ out)
{
    // plain h, double buffered, padded to 64 floats. 4 warps * 2 * 64 * 4B = 2 KB
    __shared__ float hb[WPB][2][64];

    const int tid  = threadIdx.x;
    const int w    = tid >> 5;
    const int lane = tid & 31;
    const int b    = blockIdx.x * WPB + w;

    // lanes 25..31: clamp to valid rows (compute harmless duplicates into pad)
    const int j0 = 2 * lane;
    const int r0 = (j0     < H_SZ) ? j0     : (H_SZ - 1);
    const int r1 = (j0 + 1 < H_SZ) ? j0 + 1 : (H_SZ - 1);

    // W pairs in registers: q<25 from W_hh (cols 2q,2q+1), q=25..28 from W_ih.
    ull W0[29], W1[29];
#pragma unroll
    for (int q = 0; q < 25; q++) {
        W0[q] = pack2(Whh[r0 * H_SZ + 2 * q], Whh[r0 * H_SZ + 2 * q + 1]);
        W1[q] = pack2(Whh[r1 * H_SZ + 2 * q], Whh[r1 * H_SZ + 2 * q + 1]);
    }
#pragma unroll
    for (int d = 0; d < 4; d++) {
        W0[25 + d] = pack2(Wih[r0 * DIN + 2 * d], Wih[r0 * DIN + 2 * d + 1]);
        W1[25 + d] = pack2(Wih[r1 * DIN + 2 * d], Wih[r1 * DIN + 2 * d + 1]);
    }
    const ull b0p = pack2(bih[r0] + bhh[r0], 0.0f);
    const ull b1p = pack2(bih[r1] + bhh[r1], 0.0f);
    const ull z2  = pack2(0.0f, 0.0f);

    // zero both buffers (h0 = 0; pad slots must be finite)
#pragma unroll
    for (int i = tid; i < WPB * 2 * 64; i += NTHR)
        (&hb[0][0][0])[i] = 0.0f;
    __syncthreads();

    // x row for this batch as packed pairs (16B-aligned: b*T*DIN*4 = b*16KB)
    const ulonglong2* __restrict__ xq =
        (const ulonglong2*)(x + (size_t)b * T_SZ * DIN);

    float v0 = 0.f, v1 = 0.f;

#pragma unroll 1
    for (int t = 0; t < T_SZ; t += 2) {
#pragma unroll
        for (int half = 0; half < 2; half++) {
            const int tt  = t + half;
            const int cur = half;            // read buf `half`, write buf `half^1`
            const ulonglong2 xA = xq[2 * tt];
            const ulonglong2 xB = xq[2 * tt + 1];

            // four accumulator chains: rows r0/r1 x (x-side / y-side)
            ull a0x = fma2(xA.x, W0[25], b0p);
            ull a0y = fma2(xA.y, W0[26], z2);
            ull a1x = fma2(xA.x, W1[25], b1p);
            ull a1y = fma2(xA.y, W1[26], z2);
            a0x = fma2(xB.x, W0[27], a0x);  a0y = fma2(xB.y, W0[28], a0y);
            a1x = fma2(xB.x, W1[27], a1x);  a1y = fma2(xB.y, W1[28], a1y);

            // recurrence: 12 x broadcast LDS.128 + 1 x LDS.64
            const ulonglong2* __restrict__ hp = (const ulonglong2*)hb[w][cur];
#pragma unroll
            for (int p = 0; p < 12; p++) {
                ulonglong2 hh = hp[p];                 // (h4p,h4p+1),(h4p+2,h4p+3)
                a0x = fma2(hh.x, W0[2 * p],     a0x);
                a1x = fma2(hh.x, W1[2 * p],     a1x);
                a0y = fma2(hh.y, W0[2 * p + 1], a0y);
                a1y = fma2(hh.y, W1[2 * p + 1], a1y);
            }
            {
                ull h24 = ((const ull*)hb[w][cur])[24]; // (h48,h49)
                a0x = fma2(h24, W0[24], a0x);
                a1x = fma2(h24, W1[24], a1x);
            }

            float e0, o0; unpack2(add2(a0x, a0y), e0, o0);
            float e1, o1; unpack2(add2(a1x, a1y), e1, o1);
            v0 = tanh_fast(e0 + o0);
            v1 = tanh_fast(e1 + o1);

            *(float2*)&hb[w][cur ^ 1][j0] = make_float2(v0, v1);
            __syncwarp();
        }
    }

    // fc readout: out[b] = sum_j h_T[j]*fcW[j] + fcb[0]
    float part = 0.f;
    if (lane < 25)
        part = v0 * fcW[j0] + v1 * fcW[j0 + 1];
#pragma unroll
    for (int off = 16; off; off >>= 1)
        part += __shfl_down_sync(0xffffffffu, part, off);
    if (lane == 0)
        out[b] = part + fcb[0];
}

extern "C" void kernel_launch(void* const* d_in, const int* in_sizes, int n_in,
                              void* d_out, int out_size)
{
    const float* x   = (const float*)d_in[0];
    const float* Wih = (const float*)d_in[1];
    const float* Whh = (const float*)d_in[2];
    const float* bih = (const float*)d_in[3];
    const float* bhh = (const float*)d_in[4];
    const float* fcW = (const float*)d_in[5];
    const float* fcb = (const float*)d_in[6];
    float* out = (float*)d_out;

    rnn_kernel<<<B_SZ / WPB, NTHR>>>(x, Wih, Whh, bih, bhh, fcW, fcb, out);
}